// round 3
// baseline (speedup 1.0000x reference)
#include <cuda_runtime.h>
#include <cuda_bf16.h>

#define HW      65536
#define NVEC    16384   // HW / 4
#define NB      32
#define NP      8
#define MASK_CH 9
#define KP_CH   23

// scratch[b][p][6] = {mask_cnt, mask_sx, mask_sy, kp_cnt, kp_sx, kp_sy}
__device__ int g_scratch[NB * NP * 6];

__global__ void zero_kernel() {
    int i = threadIdx.x;
    for (; i < NB * NP * 6; i += blockDim.x) g_scratch[i] = 0;
}

// Warp+block reduce 8x3 int accumulators, commit to global scratch at column
// offset `off` (0 for mask stats, 3 for keypoint stats).
__device__ __forceinline__ void reduce_commit(int b, int* cnt, int* sx, int* sy, int off) {
    __shared__ int sh[NP * 3];
    if (threadIdx.x < NP * 3) sh[threadIdx.x] = 0;
    __syncthreads();
#pragma unroll
    for (int p = 0; p < NP; p++) {
        int a = cnt[p], s1 = sx[p], s2 = sy[p];
#pragma unroll
        for (int d = 16; d > 0; d >>= 1) {
            a  += __shfl_down_sync(0xffffffffu, a,  d);
            s1 += __shfl_down_sync(0xffffffffu, s1, d);
            s2 += __shfl_down_sync(0xffffffffu, s2, d);
        }
        if ((threadIdx.x & 31) == 0) {
            atomicAdd(&sh[p * 3 + 0], a);
            atomicAdd(&sh[p * 3 + 1], s1);
            atomicAdd(&sh[p * 3 + 2], s2);
        }
    }
    __syncthreads();
    if (threadIdx.x < NP * 3) {
        int p = threadIdx.x / 3;
        int j = threadIdx.x % 3;
        atomicAdd(&g_scratch[(b * NP + p) * 6 + off + j], sh[threadIdx.x]);
    }
}

// ---- Mask centroid stats: channels 1..8, threshold 0.5 ----
__global__ void __launch_bounds__(256) mask_kernel(const float4* __restrict__ masks) {
    const int b = blockIdx.y;
    int cnt[NP], sx[NP], sy[NP];
#pragma unroll
    for (int p = 0; p < NP; p++) { cnt[p] = 0; sx[p] = 0; sy[p] = 0; }

    const float4* base = masks + (size_t)b * MASK_CH * NVEC + NVEC;  // skip channel 0
    const int stride = gridDim.x * blockDim.x;
    for (int i = blockIdx.x * blockDim.x + threadIdx.x; i < NVEC; i += stride) {
        const int pix  = i << 2;
        const int row  = pix >> 8;
        const int col0 = pix & 255;
#pragma unroll
        for (int p = 0; p < NP; p++) {
            float4 v = __ldg(base + p * NVEC + i);
            int c0 = v.x > 0.5f;
            int c1 = v.y > 0.5f;
            int c2 = v.z > 0.5f;
            int c3 = v.w > 0.5f;
            int n = c0 + c1 + c2 + c3;
            cnt[p] += n;
            sx[p]  += row * n;
            sy[p]  += n * col0 + c1 + 2 * c2 + 3 * c3;
        }
    }
    reduce_commit(b, cnt, sx, sy, 0);
}

// ---- Keypoint part-heatmap centroid stats: sum member joints, threshold 0.3 ----
__global__ void __launch_bounds__(256) kp_kernel(const float4* __restrict__ kp) {
    // joint -> primary part / secondary part (-1 = none)
    const int PA[KP_CH] = {0,0,0,0,0, 1,1,2,3,2,3, 1,1,4,5,4,5, 6,6,6,7,7,7};
    const int PB[KP_CH] = {-1,-1,-1,-1,-1, 2,3,-1,-1,-1,-1, 4,5,-1,-1,6,7,
                           -1,-1,-1,-1,-1,-1};

    const int b = blockIdx.y;
    int cnt[NP], sx[NP], sy[NP];
#pragma unroll
    for (int p = 0; p < NP; p++) { cnt[p] = 0; sx[p] = 0; sy[p] = 0; }

    const float4* base = kp + (size_t)b * KP_CH * NVEC;
    const int stride = gridDim.x * blockDim.x;
    for (int i = blockIdx.x * blockDim.x + threadIdx.x; i < NVEC; i += stride) {
        float4 s[NP];
#pragma unroll
        for (int p = 0; p < NP; p++) s[p] = make_float4(0.f, 0.f, 0.f, 0.f);

        // Each channel read exactly once; fanned into 1-2 part sums in registers.
        // Ascending-k order matches the reference einsum accumulation order.
#pragma unroll
        for (int k = 0; k < KP_CH; k++) {
            float4 v = __ldg(base + k * NVEC + i);
            int pa = PA[k];
            s[pa].x += v.x; s[pa].y += v.y; s[pa].z += v.z; s[pa].w += v.w;
            int pb = PB[k];
            if (pb >= 0) {
                s[pb].x += v.x; s[pb].y += v.y; s[pb].z += v.z; s[pb].w += v.w;
            }
        }

        const int pix  = i << 2;
        const int row  = pix >> 8;
        const int col0 = pix & 255;
#pragma unroll
        for (int p = 0; p < NP; p++) {
            int c0 = s[p].x > 0.3f;
            int c1 = s[p].y > 0.3f;
            int c2 = s[p].z > 0.3f;
            int c3 = s[p].w > 0.3f;
            int n = c0 + c1 + c2 + c3;
            cnt[p] += n;
            sx[p]  += row * n;
            sy[p]  += n * col0 + c1 + 2 * c2 + 3 * c3;
        }
    }
    reduce_commit(b, cnt, sx, sy, 3);
}

// ---- Final scalar epilogue: 256 threads = 32 batches x 8 parts ----
__global__ void __launch_bounds__(256) finalize_kernel(float* __restrict__ out) {
    const int t = threadIdx.x;
    float num = 0.f;
    float vc  = 0.f;
    {
        const int* s = &g_scratch[t * 6];
        int mc  = s[0], msx = s[1], msy = s[2];
        int kc  = s[3], ksx = s[4], ksy = s[5];

        float mdiv = fmaxf((float)mc, 1.f);
        float mmx = (float)msx / mdiv;
        float mmy = (float)msy / mdiv;
        float mcx = (mc > 0 && mmx > 0.f) ? mmx : 0.f;
        float mcy = (mc > 0 && mmy > 0.f) ? mmy : 0.f;

        float kdiv = fmaxf((float)kc, 1.f);
        float kmx = (float)ksx / kdiv;
        float kmy = (float)ksy / kdiv;
        float kcx = (kc > 0 && kmx > 0.f) ? kmx : 0.f;
        float kcy = (kc > 0 && kmy > 0.f) ? kmy : 0.f;

        bool code = (kcx == 0.f) || (kcy == 0.f) || (mcx == 0.f) || (mcy == 0.f);
        if (!code) {
            float dx = mcx - kcx;
            float dy = mcy - kcy;
            num = dx * dx + dy * dy;
            vc  = 1.f;
        }
    }

    // reduce 256 threads -> scalar
    __shared__ float shn[8], shc[8];
#pragma unroll
    for (int d = 16; d > 0; d >>= 1) {
        num += __shfl_down_sync(0xffffffffu, num, d);
        vc  += __shfl_down_sync(0xffffffffu, vc,  d);
    }
    if ((t & 31) == 0) { shn[t >> 5] = num; shc[t >> 5] = vc; }
    __syncthreads();
    if (t == 0) {
        float n = 0.f, c = 0.f;
#pragma unroll
        for (int w = 0; w < 8; w++) { n += shn[w]; c += shc[w]; }
        out[0] = 1e-5f * (n / (c * 2.0f));
    }
}

extern "C" void kernel_launch(void* const* d_in, const int* in_sizes, int n_in,
                              void* d_out, int out_size) {
    // Identify inputs by element count (robust to metadata ordering).
    const int MASK_ELEMS = NB * MASK_CH * HW;  // 18,874,368
    const float* masks;
    const float* kp;
    if (in_sizes[0] == MASK_ELEMS) {
        masks = (const float*)d_in[0];
        kp    = (const float*)d_in[1];
    } else {
        masks = (const float*)d_in[1];
        kp    = (const float*)d_in[0];
    }

    zero_kernel<<<1, 256>>>();
    mask_kernel<<<dim3(12, NB), 256>>>((const float4*)masks);
    kp_kernel<<<dim3(12, NB), 256>>>((const float4*)kp);
    finalize_kernel<<<1, 256>>>((float*)d_out);
}

// round 4
// speedup vs baseline: 1.1273x; 1.1273x over previous
#include <cuda_runtime.h>
#include <cuda_bf16.h>

#define HW      65536
#define NVEC    16384   // HW / 4
#define NB      32
#define NP      8
#define MASK_CH 9
#define KP_CH   23

#define GX        16    // blocks per batch
#define MBX       4     // of which: mask-path blocks (rest = kp-path)
#define TOTAL_BLK (GX * NB)

// scratch[b][p][6] = {mask_cnt, mask_sx, mask_sy, kp_cnt, kp_sx, kp_sy}
__device__ int g_scratch[NB * NP * 6];
__device__ unsigned int g_done;

// Warp+block reduce 8x3 int accumulators, commit to global scratch at column
// offset `off` (0 = mask stats, 3 = keypoint stats).
__device__ __forceinline__ void reduce_commit(int b, int* cnt, int* sx, int* sy, int off) {
    __shared__ int sh[NP * 3];
    if (threadIdx.x < NP * 3) sh[threadIdx.x] = 0;
    __syncthreads();
#pragma unroll
    for (int p = 0; p < NP; p++) {
        int a = cnt[p], s1 = sx[p], s2 = sy[p];
#pragma unroll
        for (int d = 16; d > 0; d >>= 1) {
            a  += __shfl_down_sync(0xffffffffu, a,  d);
            s1 += __shfl_down_sync(0xffffffffu, s1, d);
            s2 += __shfl_down_sync(0xffffffffu, s2, d);
        }
        if ((threadIdx.x & 31) == 0) {
            atomicAdd(&sh[p * 3 + 0], a);
            atomicAdd(&sh[p * 3 + 1], s1);
            atomicAdd(&sh[p * 3 + 2], s2);
        }
    }
    __syncthreads();
    if (threadIdx.x < NP * 3) {
        int p = threadIdx.x / 3;
        int j = threadIdx.x % 3;
        atomicAdd(&g_scratch[(b * NP + p) * 6 + off + j], sh[threadIdx.x]);
    }
}

__global__ void __launch_bounds__(256) fused_kernel(
    const float4* __restrict__ masks, const float4* __restrict__ kp,
    float* __restrict__ out)
{
    const int b = blockIdx.y;
    int cnt[NP], sx[NP], sy[NP];
#pragma unroll
    for (int p = 0; p < NP; p++) { cnt[p] = 0; sx[p] = 0; sy[p] = 0; }

    if (blockIdx.x < MBX) {
        // ---- Mask centroid stats: channels 1..8, threshold 0.5 ----
        const float4* base = masks + (size_t)b * MASK_CH * NVEC + NVEC;  // skip ch 0
        const int stride = MBX * 256;
        for (int i = blockIdx.x * 256 + threadIdx.x; i < NVEC; i += stride) {
            const int pix  = i << 2;
            const int row  = pix >> 8;
            const int col0 = pix & 255;
#pragma unroll
            for (int p = 0; p < NP; p++) {
                float4 v = __ldg(base + p * NVEC + i);
                int c0 = v.x > 0.5f;
                int c1 = v.y > 0.5f;
                int c2 = v.z > 0.5f;
                int c3 = v.w > 0.5f;
                int n = c0 + c1 + c2 + c3;
                cnt[p] += n;
                sx[p]  += row * n;
                sy[p]  += n * col0 + c1 + 2 * c2 + 3 * c3;
            }
        }
        reduce_commit(b, cnt, sx, sy, 0);
    } else {
        // ---- Keypoint part-heatmap stats: sum member joints, threshold 0.3 ----
        // joint -> primary part / secondary part (-1 = none)
        const int PA[KP_CH] = {0,0,0,0,0, 1,1,2,3,2,3, 1,1,4,5,4,5, 6,6,6,7,7,7};
        const int PB[KP_CH] = {-1,-1,-1,-1,-1, 2,3,-1,-1,-1,-1, 4,5,-1,-1,6,7,
                               -1,-1,-1,-1,-1,-1};
        const float4* base = kp + (size_t)b * KP_CH * NVEC;
        const int bx = blockIdx.x - MBX;
        const int stride = (GX - MBX) * 256;
        for (int i = bx * 256 + threadIdx.x; i < NVEC; i += stride) {
            float4 s[NP];
#pragma unroll
            for (int p = 0; p < NP; p++) s[p] = make_float4(0.f, 0.f, 0.f, 0.f);

            // Each channel read exactly once; fanned into 1-2 part sums.
            // Ascending-k order matches the reference einsum accumulation order.
#pragma unroll
            for (int k = 0; k < KP_CH; k++) {
                float4 v = __ldg(base + k * NVEC + i);
                int pa = PA[k];
                s[pa].x += v.x; s[pa].y += v.y; s[pa].z += v.z; s[pa].w += v.w;
                int pb = PB[k];
                if (pb >= 0) {
                    s[pb].x += v.x; s[pb].y += v.y; s[pb].z += v.z; s[pb].w += v.w;
                }
            }

            const int pix  = i << 2;
            const int row  = pix >> 8;
            const int col0 = pix & 255;
#pragma unroll
            for (int p = 0; p < NP; p++) {
                int c0 = s[p].x > 0.3f;
                int c1 = s[p].y > 0.3f;
                int c2 = s[p].z > 0.3f;
                int c3 = s[p].w > 0.3f;
                int n = c0 + c1 + c2 + c3;
                cnt[p] += n;
                sx[p]  += row * n;
                sy[p]  += n * col0 + c1 + 2 * c2 + 3 * c3;
            }
        }
        reduce_commit(b, cnt, sx, sy, 3);
    }

    // ---- Last-block finalize (threadfence-reduction pattern) ----
    __shared__ unsigned int s_last;
    __threadfence();            // make this thread's scratch atomics visible
    __syncthreads();            // cumulativity: all block's fences precede ticket
    if (threadIdx.x == 0) {
        unsigned int ticket = atomicAdd(&g_done, 1u);
        s_last = (ticket == TOTAL_BLK - 1) ? 1u : 0u;
    }
    __syncthreads();
    if (s_last == 0u) return;

    __threadfence();            // acquire: order scratch reads after observation

    const int t = threadIdx.x;  // 256 threads = 32 batches x 8 parts
    float num = 0.f, vc = 0.f;
    {
        volatile int* s = &g_scratch[t * 6];
        int mc  = s[0], msx = s[1], msy = s[2];
        int kc  = s[3], ksx = s[4], ksy = s[5];

        float mdiv = fmaxf((float)mc, 1.f);
        float mmx = (float)msx / mdiv;
        float mmy = (float)msy / mdiv;
        float mcx = (mc > 0 && mmx > 0.f) ? mmx : 0.f;
        float mcy = (mc > 0 && mmy > 0.f) ? mmy : 0.f;

        float kdiv = fmaxf((float)kc, 1.f);
        float kmx = (float)ksx / kdiv;
        float kmy = (float)ksy / kdiv;
        float kcx = (kc > 0 && kmx > 0.f) ? kmx : 0.f;
        float kcy = (kc > 0 && kmy > 0.f) ? kmy : 0.f;

        bool code = (kcx == 0.f) || (kcy == 0.f) || (mcx == 0.f) || (mcy == 0.f);
        if (!code) {
            float dx = mcx - kcx;
            float dy = mcy - kcy;
            num = dx * dx + dy * dy;
            vc  = 1.f;
        }
    }

    __shared__ float shn[8], shc[8];
#pragma unroll
    for (int d = 16; d > 0; d >>= 1) {
        num += __shfl_down_sync(0xffffffffu, num, d);
        vc  += __shfl_down_sync(0xffffffffu, vc,  d);
    }
    if ((t & 31) == 0) { shn[t >> 5] = num; shc[t >> 5] = vc; }
    __syncthreads();
    if (t == 0) {
        float n = 0.f, c = 0.f;
#pragma unroll
        for (int w = 0; w < 8; w++) { n += shn[w]; c += shc[w]; }
        out[0] = 1e-5f * (n / (c * 2.0f));
    }

    // Reset state for the next graph replay (deterministic: statics start at 0).
    __syncthreads();            // all reads of scratch done before reset
#pragma unroll
    for (int j = 0; j < 6; j++) g_scratch[t * 6 + j] = 0;
    if (t == 0) g_done = 0u;
}

extern "C" void kernel_launch(void* const* d_in, const int* in_sizes, int n_in,
                              void* d_out, int out_size) {
    // Identify inputs by element count (robust to metadata ordering).
    const int MASK_ELEMS = NB * MASK_CH * HW;  // 18,874,368
    const float* masks;
    const float* kp;
    if (in_sizes[0] == MASK_ELEMS) {
        masks = (const float*)d_in[0];
        kp    = (const float*)d_in[1];
    } else {
        masks = (const float*)d_in[1];
        kp    = (const float*)d_in[0];
    }

    fused_kernel<<<dim3(GX, NB), 256>>>((const float4*)masks,
                                        (const float4*)kp,
                                        (float*)d_out);
}

// round 7
// speedup vs baseline: 1.2139x; 1.0769x over previous
#include <cuda_runtime.h>
#include <cuda_bf16.h>

#define HW      65536
#define NVEC    16384   // HW / 4
#define NB      32
#define NP      8
#define MASK_CH 9
#define KP_CH   23

#define GX        23    // blocks per batch (6 mask + 17 kp)
#define MBX       6
#define TOTAL_BLK (GX * NB)   // 736 = ~one exact wave at 5 CTAs/SM

// scratch[b][p][6] = {mask_cnt, mask_sx, mask_sy, kp_cnt, kp_sx, kp_sy}
__device__ int g_scratch[NB * NP * 6];
__device__ unsigned int g_done;

// Unpack packed accumulators, warp+block reduce, commit to global scratch.
// sxsy[p] = (sx<<16)|sy (both < 65536 per thread); cnt packed 4 bytes/u32.
__device__ __forceinline__ void reduce_commit(int b, unsigned int* sxsy,
                                              unsigned int cntA, unsigned int cntB,
                                              int off) {
    __shared__ int sh[NP * 3];
    if (threadIdx.x < NP * 3) sh[threadIdx.x] = 0;
    __syncthreads();
#pragma unroll
    for (int p = 0; p < NP; p++) {
        int a  = (int)(((p < 4 ? cntA : cntB) >> (8 * (p & 3))) & 0xFFu);
        int s1 = (int)(sxsy[p] >> 16);
        int s2 = (int)(sxsy[p] & 0xFFFFu);
#pragma unroll
        for (int d = 16; d > 0; d >>= 1) {
            a  += __shfl_down_sync(0xffffffffu, a,  d);
            s1 += __shfl_down_sync(0xffffffffu, s1, d);
            s2 += __shfl_down_sync(0xffffffffu, s2, d);
        }
        if ((threadIdx.x & 31) == 0) {
            atomicAdd(&sh[p * 3 + 0], a);
            atomicAdd(&sh[p * 3 + 1], s1);
            atomicAdd(&sh[p * 3 + 2], s2);
        }
    }
    __syncthreads();
    if (threadIdx.x < NP * 3) {
        int p = threadIdx.x / 3;
        int j = threadIdx.x % 3;
        atomicAdd(&g_scratch[(b * NP + p) * 6 + off + j], sh[threadIdx.x]);
    }
}

__global__ void __launch_bounds__(256, 5) fused_kernel(
    const float4* __restrict__ masks, const float4* __restrict__ kp,
    float* __restrict__ out)
{
    const int b = blockIdx.y;
    unsigned int sxsy[NP];
    unsigned int cntA = 0u, cntB = 0u;
#pragma unroll
    for (int p = 0; p < NP; p++) sxsy[p] = 0u;

    // Threshold + packed accumulate for part `p` given part-sum float4 `S`,
    // pixel row and first column col0.
#define ACC(p, S, TH)                                                         \
    {                                                                         \
        int c0 = (S).x > (TH);                                                \
        int c1 = (S).y > (TH);                                                \
        int c2 = (S).z > (TH);                                                \
        int c3 = (S).w > (TH);                                                \
        int n = c0 + c1 + c2 + c3;                                            \
        sxsy[p] += ((unsigned int)(row * n) << 16)                            \
                 + (unsigned int)(n * col0 + c1 + 2 * c2 + 3 * c3);           \
        if ((p) < 4) cntA += (unsigned int)n << (8 * (p));                    \
        else         cntB += (unsigned int)n << (8 * ((p) - 4));              \
    }

    if (blockIdx.x < MBX) {
        // ---- Mask centroid stats: channels 1..8, threshold 0.5 ----
        const float4* base = masks + (size_t)b * MASK_CH * NVEC + NVEC;  // skip ch0
        const int stride = MBX * 256;
        for (int i = blockIdx.x * 256 + threadIdx.x; i < NVEC; i += stride) {
            const int pix  = i << 2;
            const int row  = pix >> 8;
            const int col0 = pix & 255;
#pragma unroll
            for (int p = 0; p < NP; p++) {
                float4 v = __ldg(base + p * NVEC + i);
                ACC(p, v, 0.5f)
            }
        }
        reduce_commit(b, sxsy, cntA, cntB, 0);
    } else {
        // ---- Keypoint part-heatmap stats: threshold 0.3 ----
        // Each channel read once, fanned into its member parts; each part is
        // thresholded the moment its last joint (ascending k, matching the
        // reference einsum order) has been added -> small live register set.
        const float4* base = kp + (size_t)b * KP_CH * NVEC;
        const int bx = blockIdx.x - MBX;
        const int stride = (GX - MBX) * 256;
        for (int i = bx * 256 + threadIdx.x; i < NVEC; i += stride) {
            const int pix  = i << 2;
            const int row  = pix >> 8;
            const int col0 = pix & 255;
            float4 v, s0, s1, s2, s3, s4, s5, s6, s7;
#define LD(k) v = __ldg(base + (k) * NVEC + i)
#define ADD4(S) { (S).x += v.x; (S).y += v.y; (S).z += v.z; (S).w += v.w; }

            LD(0);  s0 = v;
            LD(1);  ADD4(s0)
            LD(2);  ADD4(s0)
            LD(3);  ADD4(s0)
            LD(4);  ADD4(s0)  ACC(0, s0, 0.3f)          // p0: {0,1,2,3,4}
            LD(5);  s1 = v; s2 = v;
            LD(6);  ADD4(s1)  s3 = v;
            LD(7);  ADD4(s2)
            LD(8);  ADD4(s3)
            LD(9);  ADD4(s2)  ACC(2, s2, 0.3f)          // p2: {5,7,9}
            LD(10); ADD4(s3)  ACC(3, s3, 0.3f)          // p3: {6,8,10}
            LD(11); ADD4(s1)  s4 = v;
            LD(12); ADD4(s1)  s5 = v; ACC(1, s1, 0.3f)  // p1: {5,6,11,12}
            LD(13); ADD4(s4)
            LD(14); ADD4(s5)
            LD(15); ADD4(s4)  s6 = v; ACC(4, s4, 0.3f)  // p4: {11,13,15}
            LD(16); ADD4(s5)  s7 = v; ACC(5, s5, 0.3f)  // p5: {12,14,16}
            LD(17); ADD4(s6)
            LD(18); ADD4(s6)
            LD(19); ADD4(s6)  ACC(6, s6, 0.3f)          // p6: {15,17,18,19}
            LD(20); ADD4(s7)
            LD(21); ADD4(s7)
            LD(22); ADD4(s7)  ACC(7, s7, 0.3f)          // p7: {16,20,21,22}
#undef LD
#undef ADD4
        }
        reduce_commit(b, sxsy, cntA, cntB, 3);
    }
#undef ACC

    // ---- Last-block finalize (threadfence-reduction pattern) ----
    __shared__ unsigned int s_last;
    __threadfence();            // make this thread's scratch atomics visible
    __syncthreads();            // all block's fences precede the ticket
    if (threadIdx.x == 0) {
        unsigned int ticket = atomicAdd(&g_done, 1u);
        s_last = (ticket == TOTAL_BLK - 1) ? 1u : 0u;
    }
    __syncthreads();
    if (s_last == 0u) return;

    __threadfence();            // acquire: order scratch reads after observation

    const int t = threadIdx.x;  // 256 threads = 32 batches x 8 parts
    float num = 0.f, vc = 0.f;
    {
        volatile int* s = &g_scratch[t * 6];
        int mc  = s[0], msx = s[1], msy = s[2];
        int kc  = s[3], ksx = s[4], ksy = s[5];

        float mdiv = fmaxf((float)mc, 1.f);
        float mmx = (float)msx / mdiv;
        float mmy = (float)msy / mdiv;
        float mcx = (mc > 0 && mmx > 0.f) ? mmx : 0.f;
        float mcy = (mc > 0 && mmy > 0.f) ? mmy : 0.f;

        float kdiv = fmaxf((float)kc, 1.f);
        float kmx = (float)ksx / kdiv;
        float kmy = (float)ksy / kdiv;
        float kcx = (kc > 0 && kmx > 0.f) ? kmx : 0.f;
        float kcy = (kc > 0 && kmy > 0.f) ? kmy : 0.f;

        bool code = (kcx == 0.f) || (kcy == 0.f) || (mcx == 0.f) || (mcy == 0.f);
        if (!code) {
            float dx = mcx - kcx;
            float dy = mcy - kcy;
            num = dx * dx + dy * dy;
            vc  = 1.f;
        }
    }

    __shared__ float shn[8], shc[8];
#pragma unroll
    for (int d = 16; d > 0; d >>= 1) {
        num += __shfl_down_sync(0xffffffffu, num, d);
        vc  += __shfl_down_sync(0xffffffffu, vc,  d);
    }
    if ((t & 31) == 0) { shn[t >> 5] = num; shc[t >> 5] = vc; }
    __syncthreads();
    if (t == 0) {
        float n = 0.f, c = 0.f;
#pragma unroll
        for (int w = 0; w < 8; w++) { n += shn[w]; c += shc[w]; }
        out[0] = 1e-5f * (n / (c * 2.0f));
    }

    // Reset state for the next graph replay (statics start at 0 -> deterministic).
    __syncthreads();            // all reads of scratch done before reset
#pragma unroll
    for (int j = 0; j < 6; j++) g_scratch[t * 6 + j] = 0;
    if (t == 0) g_done = 0u;
}

extern "C" void kernel_launch(void* const* d_in, const int* in_sizes, int n_in,
                              void* d_out, int out_size) {
    // Identify inputs by element count (robust to metadata ordering).
    const int MASK_ELEMS = NB * MASK_CH * HW;  // 18,874,368
    const float* masks;
    const float* kp;
    if (in_sizes[0] == MASK_ELEMS) {
        masks = (const float*)d_in[0];
        kp    = (const float*)d_in[1];
    } else {
        masks = (const float*)d_in[1];
        kp    = (const float*)d_in[0];
    }

    fused_kernel<<<dim3(GX, NB), 256>>>((const float4*)masks,
                                        (const float4*)kp,
                                        (float*)d_out);
}

// round 8
// speedup vs baseline: 1.2213x; 1.0061x over previous
#include <cuda_runtime.h>
#include <cuda_bf16.h>

#define HW      65536
#define NVEC    16384   // HW / 4
#define NB      32
#define NP      8
#define MASK_CH 9
#define KP_CH   23

#define GX        23    // blocks per batch (6 mask + 17 kp)
#define MBX       6
#define TOTAL_BLK (GX * NB)

// scratch[b][p][6] = {mask_cnt, mask_sx, mask_sy, kp_cnt, kp_sx, kp_sy}
__device__ int g_scratch[NB * NP * 6];
__device__ unsigned int g_done;

// Threshold + packed accumulate for part `p` given part-sum float4 `S`.
// sxsy[p] = (sx<<16)|sy ; counts byte-packed in cntA/cntB.
#define ACC(p, S, TH)                                                         \
    {                                                                         \
        int c0 = (S).x > (TH);                                                \
        int c1 = (S).y > (TH);                                                \
        int c2 = (S).z > (TH);                                                \
        int c3 = (S).w > (TH);                                                \
        int n = c0 + c1 + c2 + c3;                                            \
        sxsy[p] += ((unsigned int)(row * n) << 16)                            \
                 + (unsigned int)(n * col0 + c1 + 2 * c2 + 3 * c3);           \
        if ((p) < 4) cntA += (unsigned int)n << (8 * (p));                    \
        else         cntB += (unsigned int)n << (8 * ((p) - 4));              \
    }

__device__ __forceinline__ void mask_body(const float4* __restrict__ base, int i,
                                          unsigned int* sxsy,
                                          unsigned int& cntA, unsigned int& cntB) {
    const int pix  = i << 2;
    const int row  = pix >> 8;
    const int col0 = pix & 255;
#pragma unroll
    for (int p = 0; p < NP; p++) {
        float4 v = __ldcs(base + p * NVEC + i);
        ACC(p, v, 0.5f)
    }
}

// Keypoint body: each channel read once (streaming), fanned into its member
// parts; each part thresholded as soon as its last joint (ascending k,
// matching the reference einsum order) is added -> small live register set.
__device__ __forceinline__ void kp_body(const float4* __restrict__ base, int i,
                                        unsigned int* sxsy,
                                        unsigned int& cntA, unsigned int& cntB) {
    const int pix  = i << 2;
    const int row  = pix >> 8;
    const int col0 = pix & 255;
    float4 v, s0, s1, s2, s3, s4, s5, s6, s7;
#define LD(k) v = __ldcs(base + (k) * NVEC + i)
#define ADD4(S) { (S).x += v.x; (S).y += v.y; (S).z += v.z; (S).w += v.w; }
    LD(0);  s0 = v;
    LD(1);  ADD4(s0)
    LD(2);  ADD4(s0)
    LD(3);  ADD4(s0)
    LD(4);  ADD4(s0)  ACC(0, s0, 0.3f)          // p0: {0,1,2,3,4}
    LD(5);  s1 = v; s2 = v;
    LD(6);  ADD4(s1)  s3 = v;
    LD(7);  ADD4(s2)
    LD(8);  ADD4(s3)
    LD(9);  ADD4(s2)  ACC(2, s2, 0.3f)          // p2: {5,7,9}
    LD(10); ADD4(s3)  ACC(3, s3, 0.3f)          // p3: {6,8,10}
    LD(11); ADD4(s1)  s4 = v;
    LD(12); ADD4(s1)  s5 = v; ACC(1, s1, 0.3f)  // p1: {5,6,11,12}
    LD(13); ADD4(s4)
    LD(14); ADD4(s5)
    LD(15); ADD4(s4)  s6 = v; ACC(4, s4, 0.3f)  // p4: {11,13,15}
    LD(16); ADD4(s5)  s7 = v; ACC(5, s5, 0.3f)  // p5: {12,14,16}
    LD(17); ADD4(s6)
    LD(18); ADD4(s6)
    LD(19); ADD4(s6)  ACC(6, s6, 0.3f)          // p6: {15,17,18,19}
    LD(20); ADD4(s7)
    LD(21); ADD4(s7)
    LD(22); ADD4(s7)  ACC(7, s7, 0.3f)          // p7: {16,20,21,22}
#undef LD
#undef ADD4
}

// Unpack packed accumulators, warp+block reduce, commit to global scratch.
__device__ __forceinline__ void reduce_commit(int b, unsigned int* sxsy,
                                              unsigned int cntA, unsigned int cntB,
                                              int off) {
    __shared__ int sh[NP * 3];
    if (threadIdx.x < NP * 3) sh[threadIdx.x] = 0;
    __syncthreads();
#pragma unroll
    for (int p = 0; p < NP; p++) {
        int a  = (int)(((p < 4 ? cntA : cntB) >> (8 * (p & 3))) & 0xFFu);
        int s1 = (int)(sxsy[p] >> 16);
        int s2 = (int)(sxsy[p] & 0xFFFFu);
#pragma unroll
        for (int d = 16; d > 0; d >>= 1) {
            a  += __shfl_down_sync(0xffffffffu, a,  d);
            s1 += __shfl_down_sync(0xffffffffu, s1, d);
            s2 += __shfl_down_sync(0xffffffffu, s2, d);
        }
        if ((threadIdx.x & 31) == 0) {
            atomicAdd(&sh[p * 3 + 0], a);
            atomicAdd(&sh[p * 3 + 1], s1);
            atomicAdd(&sh[p * 3 + 2], s2);
        }
    }
    __syncthreads();
    if (threadIdx.x < NP * 3) {
        int p = threadIdx.x / 3;
        int j = threadIdx.x % 3;
        atomicAdd(&g_scratch[(b * NP + p) * 6 + off + j], sh[threadIdx.x]);
    }
}

__global__ void __launch_bounds__(256, 4) fused_kernel(
    const float4* __restrict__ masks, const float4* __restrict__ kp,
    float* __restrict__ out)
{
    const int b = blockIdx.y;
    unsigned int sxsy[NP];
    unsigned int cntA = 0u, cntB = 0u;
#pragma unroll
    for (int p = 0; p < NP; p++) sxsy[p] = 0u;

    if (blockIdx.x < MBX) {
        // ---- Mask centroid stats: channels 1..8, threshold 0.5 ----
        const float4* base = masks + (size_t)b * MASK_CH * NVEC + NVEC;  // skip ch0
        const int stride = MBX * 256;
        for (int i = blockIdx.x * 256 + threadIdx.x; i < NVEC; i += 2 * stride) {
            mask_body(base, i, sxsy, cntA, cntB);       // two independent chains:
            int i2 = i + stride;                         // ptxas interleaves loads
            if (i2 < NVEC) mask_body(base, i2, sxsy, cntA, cntB);
        }
        reduce_commit(b, sxsy, cntA, cntB, 0);
    } else {
        // ---- Keypoint part-heatmap stats: threshold 0.3 ----
        const float4* base = kp + (size_t)b * KP_CH * NVEC;
        const int bx = blockIdx.x - MBX;
        const int stride = (GX - MBX) * 256;
        for (int i = bx * 256 + threadIdx.x; i < NVEC; i += 2 * stride) {
            kp_body(base, i, sxsy, cntA, cntB);
            int i2 = i + stride;
            if (i2 < NVEC) kp_body(base, i2, sxsy, cntA, cntB);
        }
        reduce_commit(b, sxsy, cntA, cntB, 3);
    }

    // ---- Last-block finalize (threadfence-reduction pattern) ----
    __shared__ unsigned int s_last;
    __threadfence();            // make this block's scratch atomics visible
    __syncthreads();
    if (threadIdx.x == 0) {
        unsigned int ticket = atomicAdd(&g_done, 1u);
        s_last = (ticket == TOTAL_BLK - 1) ? 1u : 0u;
    }
    __syncthreads();
    if (s_last == 0u) return;

    __threadfence();            // acquire side

    const int t = threadIdx.x;  // 256 threads = 32 batches x 8 parts
    float num = 0.f, vc = 0.f;
    {
        volatile int* s = &g_scratch[t * 6];
        int mc  = s[0], msx = s[1], msy = s[2];
        int kc  = s[3], ksx = s[4], ksy = s[5];

        float mdiv = fmaxf((float)mc, 1.f);
        float mmx = (float)msx / mdiv;
        float mmy = (float)msy / mdiv;
        float mcx = (mc > 0 && mmx > 0.f) ? mmx : 0.f;
        float mcy = (mc > 0 && mmy > 0.f) ? mmy : 0.f;

        float kdiv = fmaxf((float)kc, 1.f);
        float kmx = (float)ksx / kdiv;
        float kmy = (float)ksy / kdiv;
        float kcx = (kc > 0 && kmx > 0.f) ? kmx : 0.f;
        float kcy = (kc > 0 && kmy > 0.f) ? kmy : 0.f;

        bool code = (kcx == 0.f) || (kcy == 0.f) || (mcx == 0.f) || (mcy == 0.f);
        if (!code) {
            float dx = mcx - kcx;
            float dy = mcy - kcy;
            num = dx * dx + dy * dy;
            vc  = 1.f;
        }
    }

    __shared__ float shn[8], shc[8];
#pragma unroll
    for (int d = 16; d > 0; d >>= 1) {
        num += __shfl_down_sync(0xffffffffu, num, d);
        vc  += __shfl_down_sync(0xffffffffu, vc,  d);
    }
    if ((t & 31) == 0) { shn[t >> 5] = num; shc[t >> 5] = vc; }
    __syncthreads();
    if (t == 0) {
        float n = 0.f, c = 0.f;
#pragma unroll
        for (int w = 0; w < 8; w++) { n += shn[w]; c += shc[w]; }
        out[0] = 1e-5f * (n / (c * 2.0f));
    }

    // Reset state for the next graph replay (statics start at 0 -> deterministic).
    __syncthreads();
#pragma unroll
    for (int j = 0; j < 6; j++) g_scratch[t * 6 + j] = 0;
    if (t == 0) g_done = 0u;
}

extern "C" void kernel_launch(void* const* d_in, const int* in_sizes, int n_in,
                              void* d_out, int out_size) {
    // Identify inputs by element count (robust to metadata ordering).
    const int MASK_ELEMS = NB * MASK_CH * HW;  // 18,874,368
    const float* masks;
    const float* kp;
    if (in_sizes[0] == MASK_ELEMS) {
        masks = (const float*)d_in[0];
        kp    = (const float*)d_in[1];
    } else {
        masks = (const float*)d_in[1];
        kp    = (const float*)d_in[0];
    }

    fused_kernel<<<dim3(GX, NB), 256>>>((const float4*)masks,
                                        (const float4*)kp,
                                        (float*)d_out);
}